// round 1
// baseline (speedup 1.0000x reference)
#include <cuda_runtime.h>
#include <cuda_bf16.h>

// Problem constants
#define B      2
#define S      4096      // 16*16*16
#define DIM    64
#define HEADS  4
#define DHEAD  32
#define HIDDEN (HEADS*DHEAD)   // 128
#define BH     (B*HEADS)       // 8
#define NROWS  (B*S)           // 8192
#define SCALE  16.0f
#define EPS    1e-5f

// Scratch (no allocations allowed)
__device__ float g_q[BH * S * DHEAD];     // [bh][s][d]
__device__ float g_k[BH * S * DHEAD];
__device__ float g_v[BH * S * DHEAD];
__device__ float g_mean[2][BH][DHEAD];    // [0]=q, [1]=k
__device__ float g_rstd[2][BH][DHEAD];
__device__ float g_o[B * S * HIDDEN];     // [b][s][h][d]

// ---------------------------------------------------------------------------
// K1: qkv = input @ w_qkv, scattered into q/k/v [bh][s][d]
// One block per token row (8192 blocks), 384 threads = one output column each.
// ---------------------------------------------------------------------------
__global__ void qkv_kernel(const float* __restrict__ inp,
                           const float* __restrict__ w_qkv) {
    __shared__ float sh[DIM];
    int row = blockIdx.x;            // 0..8191
    int c   = threadIdx.x;           // 0..383
    if (c < DIM) sh[c] = inp[row * DIM + c];
    __syncthreads();

    float acc = 0.f;
#pragma unroll
    for (int k = 0; k < DIM; k++)
        acc = fmaf(sh[k], w_qkv[k * 384 + c], acc);

    int b = row >> 12;               // row / 4096
    int s = row & 4095;
    int part = c >> 7;               // 0=q, 1=k, 2=v
    int hc = c & 127;
    int h = hc >> 5, d = hc & 31;
    float* dst = (part == 0) ? g_q : (part == 1) ? g_k : g_v;
    dst[(((b * HEADS + h) * S) + s) * DHEAD + d] = acc;
}

// ---------------------------------------------------------------------------
// K2: per-(b,h,d) mean / rstd over s for q and k.
// grid (BH, 2), block 256 (8 warps x 32 lanes; lane = d).
// ---------------------------------------------------------------------------
__global__ void stats_kernel() {
    int bh = blockIdx.x;
    int qk = blockIdx.y;             // 0=q, 1=k
    const float* src = ((qk == 0) ? g_q : g_k) + bh * S * DHEAD;
    int lane = threadIdx.x & 31;
    int warp = threadIdx.x >> 5;

    float sum = 0.f, ss = 0.f;
    for (int s = warp; s < S; s += 8) {
        float v = src[s * DHEAD + lane];
        sum += v;
        ss = fmaf(v, v, ss);
    }
    __shared__ float shs[8][32], shss[8][32];
    shs[warp][lane] = sum;
    shss[warp][lane] = ss;
    __syncthreads();
    if (warp == 0) {
        float t = 0.f, t2 = 0.f;
#pragma unroll
        for (int w = 0; w < 8; w++) { t += shs[w][lane]; t2 += shss[w][lane]; }
        float mean = t * (1.f / (float)S);
        float var  = t2 * (1.f / (float)S) - mean * mean;
        g_mean[qk][bh][lane] = mean;
        g_rstd[qk][bh][lane] = rsqrtf(var + EPS);
    }
}

// ---------------------------------------------------------------------------
// K3: flash attention per (b,h). 64 queries / block, 1 query / thread.
// K/V tiles of 64 rows in shared; scores in 32-wide register sub-tiles.
// Standardization (+SCALE folded into q) applied on load.
// ---------------------------------------------------------------------------
__global__ __launch_bounds__(64) void attn_kernel() {
    int bh  = blockIdx.y;
    int tid = threadIdx.x;
    const float* qp = g_q + bh * S * DHEAD;
    const float* kp = g_k + bh * S * DHEAD;
    const float* vp = g_v + bh * S * DHEAD;

    __shared__ float ksh[64][DHEAD];
    __shared__ float vsh[64][DHEAD];
    __shared__ float kscale[DHEAD], kbias[DHEAD];

    if (tid < DHEAD) {
        float mu = g_mean[1][bh][tid], rs = g_rstd[1][bh][tid];
        kscale[tid] = rs;
        kbias[tid]  = -mu * rs;
    }
    __syncthreads();

    // Load + normalize this thread's query (scale folded in)
    int qi = blockIdx.x * 64 + tid;
    float qv[DHEAD];
#pragma unroll
    for (int d = 0; d < DHEAD; d++) {
        float mu = g_mean[0][bh][d], rs = g_rstd[0][bh][d];
        qv[d] = (qp[qi * DHEAD + d] - mu) * (rs * SCALE);
    }

    float m = -1e30f, l = 0.f;
    float acc[DHEAD];
#pragma unroll
    for (int d = 0; d < DHEAD; d++) acc[d] = 0.f;

    for (int j0 = 0; j0 < S; j0 += 64) {
        __syncthreads();
        // cooperative tile load (float4, normalized k)
        const float4* kp4 = (const float4*)(kp + j0 * DHEAD);
        const float4* vp4 = (const float4*)(vp + j0 * DHEAD);
#pragma unroll
        for (int i = 0; i < 8; i++) {
            int idx = tid + i * 64;          // float4 index 0..511
            int j  = idx >> 3;               // 8 float4 per row
            int d4 = (idx & 7) * 4;
            float4 kk = kp4[idx];
            float4 vv = vp4[idx];
            kk.x = fmaf(kk.x, kscale[d4],     kbias[d4]);
            kk.y = fmaf(kk.y, kscale[d4 + 1], kbias[d4 + 1]);
            kk.z = fmaf(kk.z, kscale[d4 + 2], kbias[d4 + 2]);
            kk.w = fmaf(kk.w, kscale[d4 + 3], kbias[d4 + 3]);
            *(float4*)&ksh[j][d4] = kk;
            *(float4*)&vsh[j][d4] = vv;
        }
        __syncthreads();

#pragma unroll
        for (int half = 0; half < 2; half++) {
            float sv[32];
#pragma unroll
            for (int jj = 0; jj < 32; jj++) {
                int j = half * 32 + jj;
                float s = 0.f;
#pragma unroll
                for (int d = 0; d < DHEAD; d += 4) {
                    float4 kk = *(const float4*)&ksh[j][d];
                    s = fmaf(qv[d],     kk.x, s);
                    s = fmaf(qv[d + 1], kk.y, s);
                    s = fmaf(qv[d + 2], kk.z, s);
                    s = fmaf(qv[d + 3], kk.w, s);
                }
                sv[jj] = s;
            }
            float tm = sv[0];
#pragma unroll
            for (int jj = 1; jj < 32; jj++) tm = fmaxf(tm, sv[jj]);
            if (tm > m) {
                float corr = __expf(m - tm);
                m = tm;
                l *= corr;
#pragma unroll
                for (int d = 0; d < DHEAD; d++) acc[d] *= corr;
            }
#pragma unroll
            for (int jj = 0; jj < 32; jj++) {
                int j = half * 32 + jj;
                float p = __expf(sv[jj] - m);
                l += p;
#pragma unroll
                for (int d = 0; d < DHEAD; d += 4) {
                    float4 vv = *(const float4*)&vsh[j][d];
                    acc[d]     = fmaf(p, vv.x, acc[d]);
                    acc[d + 1] = fmaf(p, vv.y, acc[d + 1]);
                    acc[d + 2] = fmaf(p, vv.z, acc[d + 2]);
                    acc[d + 3] = fmaf(p, vv.w, acc[d + 3]);
                }
            }
        }
    }

    float inv = 1.f / l;
    int b = bh >> 2, h = bh & 3;
    float* op = g_o + ((b * S + qi) * HEADS + h) * DHEAD;
#pragma unroll
    for (int d = 0; d < DHEAD; d += 4) {
        float4 o4 = make_float4(acc[d] * inv, acc[d + 1] * inv,
                                acc[d + 2] * inv, acc[d + 3] * inv);
        *(float4*)(op + d) = o4;
    }
}

// ---------------------------------------------------------------------------
// K4: out = o @ w_out + b_out. One block per token row, 64 threads = 64 cols.
// ---------------------------------------------------------------------------
__global__ void out_kernel(const float* __restrict__ w_out,
                           const float* __restrict__ b_out,
                           float* __restrict__ out) {
    __shared__ float sh[HIDDEN];
    int row = blockIdx.x;
    int c   = threadIdx.x;           // 0..63
    sh[c]       = g_o[row * HIDDEN + c];
    sh[c + 64]  = g_o[row * HIDDEN + 64 + c];
    __syncthreads();

    float acc = b_out[c];
#pragma unroll
    for (int k = 0; k < HIDDEN; k++)
        acc = fmaf(sh[k], w_out[k * DIM + c], acc);
    out[row * DIM + c] = acc;
}

// ---------------------------------------------------------------------------
extern "C" void kernel_launch(void* const* d_in, const int* in_sizes, int n_in,
                              void* d_out, int out_size) {
    const float* inp   = (const float*)d_in[0];
    const float* w_qkv = (const float*)d_in[1];
    const float* w_out = (const float*)d_in[2];
    const float* b_out = (const float*)d_in[3];
    float* out = (float*)d_out;

    qkv_kernel<<<NROWS, 384>>>(inp, w_qkv);
    stats_kernel<<<dim3(BH, 2), 256>>>();
    attn_kernel<<<dim3(S / 64, BH), 64>>>();
    out_kernel<<<NROWS, 64>>>(w_out, b_out, out);
}

// round 4
// speedup vs baseline: 1.6905x; 1.6905x over previous
#include <cuda_runtime.h>
#include <cuda_bf16.h>
#include <cstdint>

// Problem constants
#define B      2
#define S      4096      // 16*16*16
#define DIM    64
#define HEADS  4
#define DHEAD  32
#define HIDDEN (HEADS*DHEAD)   // 128
#define BH     (B*HEADS)       // 8
#define NROWS  (B*S)           // 8192
#define SCALE  16.0f
#define EPS    1e-5f

// Scratch (no allocations allowed)
__device__ float g_q[BH * S * DHEAD];     // [bh][s][d]
__device__ float g_k[BH * S * DHEAD];
__device__ float g_v[BH * S * DHEAD];
__device__ float g_mean[2][BH][DHEAD];    // [0]=q, [1]=k
__device__ float g_rstd[2][BH][DHEAD];
__device__ float g_o[B * S * HIDDEN];     // [b][s][h][d]

// ---------------------------------------------------------------------------
// helpers
// ---------------------------------------------------------------------------
__device__ __forceinline__ float tf32r(float x) {
    uint32_t u;
    asm("cvt.rna.tf32.f32 %0, %1;" : "=r"(u) : "f"(x));
    return __uint_as_float(u);
}

__device__ __forceinline__ void mma_tf32(float* d, const uint32_t* a,
                                         uint32_t b0, uint32_t b1,
                                         const float* c) {
    asm volatile(
        "mma.sync.aligned.m16n8k8.row.col.f32.tf32.tf32.f32 "
        "{%0,%1,%2,%3}, {%4,%5,%6,%7}, {%8,%9}, {%10,%11,%12,%13};\n"
        : "=f"(d[0]), "=f"(d[1]), "=f"(d[2]), "=f"(d[3])
        : "r"(a[0]), "r"(a[1]), "r"(a[2]), "r"(a[3]),
          "r"(b0), "r"(b1),
          "f"(c[0]), "f"(c[1]), "f"(c[2]), "f"(c[3]));
}

// ---------------------------------------------------------------------------
// K1: qkv = input @ w_qkv, scattered into q/k/v [bh][s][d]
// ---------------------------------------------------------------------------
__global__ void qkv_kernel(const float* __restrict__ inp,
                           const float* __restrict__ w_qkv) {
    __shared__ float sh[DIM];
    int row = blockIdx.x;
    int c   = threadIdx.x;           // 0..383
    if (c < DIM) sh[c] = inp[row * DIM + c];
    __syncthreads();

    float acc = 0.f;
#pragma unroll
    for (int k = 0; k < DIM; k++)
        acc = fmaf(sh[k], w_qkv[k * 384 + c], acc);

    int b = row >> 12;
    int s = row & 4095;
    int part = c >> 7;               // 0=q, 1=k, 2=v
    int hc = c & 127;
    int h = hc >> 5, d = hc & 31;
    float* dst = (part == 0) ? g_q : (part == 1) ? g_k : g_v;
    dst[(((b * HEADS + h) * S) + s) * DHEAD + d] = acc;
}

// ---------------------------------------------------------------------------
// K2: per-(b,h,d) mean / rstd over s for q and k.
// ---------------------------------------------------------------------------
__global__ void stats_kernel() {
    int bh = blockIdx.x;
    int qk = blockIdx.y;
    const float* src = ((qk == 0) ? g_q : g_k) + bh * S * DHEAD;
    int lane = threadIdx.x & 31;
    int warp = threadIdx.x >> 5;

    float sum = 0.f, ss = 0.f;
    for (int s = warp; s < S; s += 8) {
        float v = src[s * DHEAD + lane];
        sum += v;
        ss = fmaf(v, v, ss);
    }
    __shared__ float shs[8][32], shss[8][32];
    shs[warp][lane] = sum;
    shss[warp][lane] = ss;
    __syncthreads();
    if (warp == 0) {
        float t = 0.f, t2 = 0.f;
#pragma unroll
        for (int w = 0; w < 8; w++) { t += shs[w][lane]; t2 += shss[w][lane]; }
        float mean = t * (1.f / (float)S);
        float var  = t2 * (1.f / (float)S) - mean * mean;
        g_mean[qk][bh][lane] = mean;
        g_rstd[qk][bh][lane] = rsqrtf(var + EPS);
    }
}

// ---------------------------------------------------------------------------
// K3: flash attention with tf32 mma.sync; QK^T uses 3xTF32 error compensation
// (q = q_hi + q_lo, k = k_hi + k_lo; s = qh*kh + qh*kl + ql*kh).
// Block: 128 threads = 4 warps, each warp owns 16 queries. Key tiles of 64.
// ---------------------------------------------------------------------------
#define KP 36
#define PP 68
__global__ __launch_bounds__(128) void attn_mma_kernel() {
    __shared__ float ksh[64][KP];      // k_hi (normalized, tf32)
    __shared__ float kshl[64][KP];     // k_lo residual (tf32)
    __shared__ float vsh[64][KP];      // v (tf32)
    __shared__ float psh[4][16][PP];
    __shared__ float kscale[DHEAD], kbias[DHEAD];

    int bh   = blockIdx.y;
    int tid  = threadIdx.x;
    int warp = tid >> 5;
    int lane = tid & 31;
    int gid  = lane >> 2;            // 0..7
    int tig  = lane & 3;             // 0..3

    const float* qp = g_q + bh * S * DHEAD;
    const float* kp = g_k + bh * S * DHEAD;
    const float* vp = g_v + bh * S * DHEAD;

    if (tid < DHEAD) {
        float mu = g_mean[1][bh][tid], rs = g_rstd[1][bh][tid];
        kscale[tid] = rs;
        kbias[tid]  = -mu * rs;
    }
    __syncthreads();

    // -------- Q fragments: hi + lo split (normalized, SCALE folded) --------
    int q0 = blockIdx.x * 64 + warp * 16;
    uint32_t qf[4][4], qfl[4][4];
#pragma unroll
    for (int ks = 0; ks < 4; ks++) {
        int c0 = ks * 8 + tig;
#pragma unroll
        for (int ci = 0; ci < 2; ci++) {
            int c = c0 + ci * 4;
            float mu = g_mean[0][bh][c], rs = g_rstd[0][bh][c] * SCALE;
            float v0 = (qp[(q0 + gid) * DHEAD + c] - mu) * rs;
            float v1 = (qp[(q0 + gid + 8) * DHEAD + c] - mu) * rs;
            float h0 = tf32r(v0), h1 = tf32r(v1);
            qf[ks][ci * 2 + 0]  = __float_as_uint(h0);
            qf[ks][ci * 2 + 1]  = __float_as_uint(h1);
            qfl[ks][ci * 2 + 0] = __float_as_uint(tf32r(v0 - h0));
            qfl[ks][ci * 2 + 1] = __float_as_uint(tf32r(v1 - h1));
        }
    }

    float oacc[4][4];
#pragma unroll
    for (int i = 0; i < 4; i++)
#pragma unroll
        for (int j = 0; j < 4; j++) oacc[i][j] = 0.f;
    float m0 = -1e30f, m1 = -1e30f, l0 = 0.f, l1 = 0.f;

    for (int j0 = 0; j0 < S; j0 += 64) {
        __syncthreads();
        // cooperative K/V tile load (normalize K, hi/lo split; V tf32)
        const float4* kp4 = (const float4*)(kp + j0 * DHEAD);
        const float4* vp4 = (const float4*)(vp + j0 * DHEAD);
#pragma unroll
        for (int i = 0; i < 4; i++) {
            int idx = tid + i * 128;     // 0..511 float4s
            int j   = idx >> 3;
            int d4  = (idx & 7) * 4;
            float4 kk = kp4[idx];
            float4 vv = vp4[idx];
            float n0 = fmaf(kk.x, kscale[d4 + 0], kbias[d4 + 0]);
            float n1 = fmaf(kk.y, kscale[d4 + 1], kbias[d4 + 1]);
            float n2 = fmaf(kk.z, kscale[d4 + 2], kbias[d4 + 2]);
            float n3 = fmaf(kk.w, kscale[d4 + 3], kbias[d4 + 3]);
            float h0 = tf32r(n0), h1 = tf32r(n1), h2 = tf32r(n2), h3 = tf32r(n3);
            ksh[j][d4 + 0] = h0;  kshl[j][d4 + 0] = tf32r(n0 - h0);
            ksh[j][d4 + 1] = h1;  kshl[j][d4 + 1] = tf32r(n1 - h1);
            ksh[j][d4 + 2] = h2;  kshl[j][d4 + 2] = tf32r(n2 - h2);
            ksh[j][d4 + 3] = h3;  kshl[j][d4 + 3] = tf32r(n3 - h3);
            vsh[j][d4 + 0] = tf32r(vv.x);
            vsh[j][d4 + 1] = tf32r(vv.y);
            vsh[j][d4 + 2] = tf32r(vv.z);
            vsh[j][d4 + 3] = tf32r(vv.w);
        }
        __syncthreads();

        // -------- QK^T: 16x64 scores, 3xTF32 --------
        float sc[8][4];
#pragma unroll
        for (int nt = 0; nt < 8; nt++) {
#pragma unroll
            for (int j = 0; j < 4; j++) sc[nt][j] = 0.f;
#pragma unroll
            for (int ks = 0; ks < 4; ks++) {
                int r = nt * 8 + gid, c = ks * 8 + tig;
                uint32_t bh0 = __float_as_uint(ksh[r][c]);
                uint32_t bh1 = __float_as_uint(ksh[r][c + 4]);
                uint32_t bl0 = __float_as_uint(kshl[r][c]);
                uint32_t bl1 = __float_as_uint(kshl[r][c + 4]);
                mma_tf32(sc[nt], qf[ks],  bh0, bh1, sc[nt]);
                mma_tf32(sc[nt], qf[ks],  bl0, bl1, sc[nt]);
                mma_tf32(sc[nt], qfl[ks], bh0, bh1, sc[nt]);
            }
        }

        // -------- online softmax --------
        float tm0 = -1e30f, tm1 = -1e30f;
#pragma unroll
        for (int nt = 0; nt < 8; nt++) {
            tm0 = fmaxf(tm0, fmaxf(sc[nt][0], sc[nt][1]));
            tm1 = fmaxf(tm1, fmaxf(sc[nt][2], sc[nt][3]));
        }
        tm0 = fmaxf(tm0, __shfl_xor_sync(0xffffffffu, tm0, 1));
        tm0 = fmaxf(tm0, __shfl_xor_sync(0xffffffffu, tm0, 2));
        tm1 = fmaxf(tm1, __shfl_xor_sync(0xffffffffu, tm1, 1));
        tm1 = fmaxf(tm1, __shfl_xor_sync(0xffffffffu, tm1, 2));

        if (tm0 > m0) {
            float corr = __expf(m0 - tm0);
            m0 = tm0; l0 *= corr;
#pragma unroll
            for (int nt = 0; nt < 4; nt++) { oacc[nt][0] *= corr; oacc[nt][1] *= corr; }
        }
        if (tm1 > m1) {
            float corr = __expf(m1 - tm1);
            m1 = tm1; l1 *= corr;
#pragma unroll
            for (int nt = 0; nt < 4; nt++) { oacc[nt][2] *= corr; oacc[nt][3] *= corr; }
        }

#pragma unroll
        for (int nt = 0; nt < 8; nt++) {
            float p0 = tf32r(__expf(sc[nt][0] - m0));
            float p1 = tf32r(__expf(sc[nt][1] - m0));
            float p2 = tf32r(__expf(sc[nt][2] - m1));
            float p3 = tf32r(__expf(sc[nt][3] - m1));
            l0 += p0 + p1; l1 += p2 + p3;
            *(float2*)&psh[warp][gid][nt * 8 + 2 * tig]     = make_float2(p0, p1);
            *(float2*)&psh[warp][gid + 8][nt * 8 + 2 * tig] = make_float2(p2, p3);
        }
        __syncwarp();

        // -------- P @ V : 16x32 --------
#pragma unroll
        for (int ks2 = 0; ks2 < 8; ks2++) {
            uint32_t a[4];
            a[0] = __float_as_uint(psh[warp][gid][ks2 * 8 + tig]);
            a[1] = __float_as_uint(psh[warp][gid + 8][ks2 * 8 + tig]);
            a[2] = __float_as_uint(psh[warp][gid][ks2 * 8 + tig + 4]);
            a[3] = __float_as_uint(psh[warp][gid + 8][ks2 * 8 + tig + 4]);
#pragma unroll
            for (int nt2 = 0; nt2 < 4; nt2++) {
                uint32_t b0 = __float_as_uint(vsh[ks2 * 8 + tig][nt2 * 8 + gid]);
                uint32_t b1 = __float_as_uint(vsh[ks2 * 8 + tig + 4][nt2 * 8 + gid]);
                mma_tf32(oacc[nt2], a, b0, b1, oacc[nt2]);
            }
        }
    }

    // -------- reduce softmax denominator across the 4-lane group --------
    l0 += __shfl_xor_sync(0xffffffffu, l0, 1);
    l0 += __shfl_xor_sync(0xffffffffu, l0, 2);
    l1 += __shfl_xor_sync(0xffffffffu, l1, 1);
    l1 += __shfl_xor_sync(0xffffffffu, l1, 2);

    // -------- epilogue --------
    float inv0 = 1.f / l0, inv1 = 1.f / l1;
    int bb = bh >> 2, h = bh & 3;
    int r0 = q0 + gid;
    float* op0 = g_o + ((bb * S + r0) * HEADS + h) * DHEAD;
    float* op1 = g_o + ((bb * S + r0 + 8) * HEADS + h) * DHEAD;
#pragma unroll
    for (int nt2 = 0; nt2 < 4; nt2++) {
        int c = nt2 * 8 + 2 * tig;
        *(float2*)(op0 + c) = make_float2(oacc[nt2][0] * inv0, oacc[nt2][1] * inv0);
        *(float2*)(op1 + c) = make_float2(oacc[nt2][2] * inv1, oacc[nt2][3] * inv1);
    }
}

// ---------------------------------------------------------------------------
// K4: out = o @ w_out + b_out.
// ---------------------------------------------------------------------------
__global__ void out_kernel(const float* __restrict__ w_out,
                           const float* __restrict__ b_out,
                           float* __restrict__ out) {
    __shared__ float sh[HIDDEN];
    int row = blockIdx.x;
    int c   = threadIdx.x;           // 0..63
    sh[c]       = g_o[row * HIDDEN + c];
    sh[c + 64]  = g_o[row * HIDDEN + 64 + c];
    __syncthreads();

    float acc = b_out[c];
#pragma unroll
    for (int k = 0; k < HIDDEN; k++)
        acc = fmaf(sh[k], w_out[k * DIM + c], acc);
    out[row * DIM + c] = acc;
}

// ---------------------------------------------------------------------------
extern "C" void kernel_launch(void* const* d_in, const int* in_sizes, int n_in,
                              void* d_out, int out_size) {
    const float* inp   = (const float*)d_in[0];
    const float* w_qkv = (const float*)d_in[1];
    const float* w_out = (const float*)d_in[2];
    const float* b_out = (const float*)d_in[3];
    float* out = (float*)d_out;

    qkv_kernel<<<NROWS, 384>>>(inp, w_qkv);
    stats_kernel<<<dim3(BH, 2), 256>>>();
    attn_mma_kernel<<<dim3(S / 64, BH), 128>>>();
    out_kernel<<<NROWS, 64>>>(w_out, b_out, out);
}